// round 5
// baseline (speedup 1.0000x reference)
#include <cuda_runtime.h>
#include <cuda_fp16.h>
#include <cstdint>

// ---------------- Problem dims ----------------
static constexpr int T   = 20;
static constexpr int B   = 1024;
static constexpr int IN  = 2048;
static constexpr int OUT = 2048;
static constexpr int M   = T * B;          // 20480
static constexpr int K   = IN;             // 2048
static constexpr int N   = OUT;            // 2048

// GEMM tiling (Ampere-style mma.sync path; sm_103 base target has no tcgen05)
static constexpr int BM = 128;
static constexpr int BN = 128;
static constexpr int BK = 64;
static constexpr int STAGES = 3;
static constexpr int NCHUNK = K / BK;      // 32

static constexpr int PAD    = 72;                 // smem row stride in halfs (144B)
static constexpr int MAT_B  = 128 * PAD * 2;      // 18432 B per matrix tile
static constexpr int STAGE_B = 3 * MAT_B;         // A + Bhi + Blo = 55296 B
static constexpr int SMEM_B  = STAGES * STAGE_B;  // 165888 B

// ---------------- scratch (no cudaMalloc allowed) ----------------
__device__ __half g_xh [(size_t)M * K];    // 84 MB  x in fp16 (exact: x is 0/1)
__device__ __half g_whi[(size_t)N * K];    // 8 MB   weight hi (fp16)
__device__ __half g_wlo[(size_t)N * K];    // 8 MB   weight lo (fp16 residual)
__device__ float  g_cur[(size_t)M * N];    // 168 MB GEMM result (fp32)

// ---------------- helpers ----------------
__device__ __forceinline__ uint32_t smem_u32(const void* p) {
    uint32_t a;
    asm("{ .reg .u64 t; cvta.to.shared.u64 t, %1; cvt.u32.u64 %0, t; }" : "=r"(a) : "l"(p));
    return a;
}
__device__ __forceinline__ void cp16(uint32_t dst, const void* src) {
    asm volatile("cp.async.cg.shared.global [%0], [%1], 16;\n" :: "r"(dst), "l"(src));
}
__device__ __forceinline__ void ldm_x4(uint32_t* r, uint32_t addr) {
    asm volatile("ldmatrix.sync.aligned.m8n8.x4.shared.b16 {%0,%1,%2,%3}, [%4];"
                 : "=r"(r[0]), "=r"(r[1]), "=r"(r[2]), "=r"(r[3]) : "r"(addr));
}
__device__ __forceinline__ void mma16816(float* d, const uint32_t* a, uint32_t b0, uint32_t b1) {
    asm volatile(
        "mma.sync.aligned.m16n8k16.row.col.f32.f16.f16.f32 "
        "{%0,%1,%2,%3}, {%4,%5,%6,%7}, {%8,%9}, {%0,%1,%2,%3};"
        : "+f"(d[0]), "+f"(d[1]), "+f"(d[2]), "+f"(d[3])
        : "r"(a[0]), "r"(a[1]), "r"(a[2]), "r"(a[3]), "r"(b0), "r"(b1));
}

// ---------------- prep kernels ----------------
__global__ void split_w_kernel(const float* __restrict__ w) {
    int i = blockIdx.x * blockDim.x + threadIdx.x;
    if (i < N * K) {
        float v = w[i];
        __half hi = __float2half_rn(v);
        float r = v - __half2float(hi);
        g_whi[i] = hi;
        g_wlo[i] = __float2half_rn(r);
    }
}

__global__ void conv_x_kernel(const float* __restrict__ x) {
    size_t i = (size_t)blockIdx.x * blockDim.x + threadIdx.x;   // one float4 per thread
    if (i < ((size_t)M * K) / 4) {
        float4 v = reinterpret_cast<const float4*>(x)[i];
        __half2 h0 = __floats2half2_rn(v.x, v.y);
        __half2 h1 = __floats2half2_rn(v.z, v.w);
        uint2 packed;
        packed.x = *reinterpret_cast<uint32_t*>(&h0);
        packed.y = *reinterpret_cast<uint32_t*>(&h1);
        reinterpret_cast<uint2*>(g_xh)[i] = packed;
    }
}

// ---------------- GEMM kernel: 128x128x64 tiles, 3-stage cp.async, mma.sync fp16 2-split ----
__global__ void __launch_bounds__(256, 1) gemm_kernel() {
    extern __shared__ char smem[];
    const uint32_t sb = smem_u32(smem);
    const int tid = threadIdx.x;
    const int lid = tid & 31;
    const int wid = tid >> 5;

    const int m0 = blockIdx.y * BM;
    const int n0 = blockIdx.x * BN;

    // warp layout: 2 (m) x 4 (n), warp tile 64x32
    const int wm = (wid & 1) * 64;
    const int wn = (wid >> 1) * 32;

    // ldmatrix lane addressing (precomputed)
    const int a_row = wm + (lid & 15);
    const int a_kh  = (lid >> 4) << 3;                         // 0 or 8
    const int b_n   = wn + (lid & 7) + ((lid >> 4) << 3);      // n row within tile
    const int b_kh  = ((lid >> 3) & 1) << 3;                   // 0 or 8

    auto issue = [&](int c) {
        if (c < NCHUNK) {
            const int k0 = c * BK;
            const uint32_t base = sb + (c % STAGES) * STAGE_B;
            #pragma unroll
            for (int i = 0; i < 4; i++) {
                int id = tid + i * 256;
                int row = id >> 3, kc = id & 7;
                cp16(base + row * 144 + kc * 16,
                     g_xh + (size_t)(m0 + row) * K + k0 + kc * 8);
            }
            #pragma unroll
            for (int i = 0; i < 4; i++) {
                int id = tid + i * 256;
                int row = id >> 3, kc = id & 7;
                const size_t goff = (size_t)(n0 + row) * K + k0 + kc * 8;
                const uint32_t soff = row * 144 + kc * 16;
                cp16(base + MAT_B     + soff, g_whi + goff);
                cp16(base + 2 * MAT_B + soff, g_wlo + goff);
            }
        }
        asm volatile("cp.async.commit_group;\n" ::: "memory");
    };

    issue(0);
    issue(1);

    float acc[4][4][4];
    #pragma unroll
    for (int i = 0; i < 4; i++)
        #pragma unroll
        for (int j = 0; j < 4; j++)
            #pragma unroll
            for (int r = 0; r < 4; r++) acc[i][j][r] = 0.0f;

    #pragma unroll 1
    for (int c = 0; c < NCHUNK; c++) {
        asm volatile("cp.async.wait_group 1;\n" ::: "memory");
        __syncthreads();
        issue(c + 2);

        const uint32_t sA  = sb + (c % STAGES) * STAGE_B;
        const uint32_t sBh = sA + MAT_B;
        const uint32_t sBl = sA + 2 * MAT_B;

        #pragma unroll
        for (int ks = 0; ks < 4; ks++) {
            uint32_t a[4][4];
            #pragma unroll
            for (int mi = 0; mi < 4; mi++) {
                uint32_t addr = sA + (uint32_t)((a_row + mi * 16) * PAD + ks * 16 + a_kh) * 2;
                ldm_x4(a[mi], addr);
            }
            uint32_t bh[2][4], bl[2][4];
            #pragma unroll
            for (int bi = 0; bi < 2; bi++) {
                uint32_t off = (uint32_t)((b_n + bi * 16) * PAD + ks * 16 + b_kh) * 2;
                ldm_x4(bh[bi], sBh + off);
                ldm_x4(bl[bi], sBl + off);
            }
            #pragma unroll
            for (int mi = 0; mi < 4; mi++) {
                #pragma unroll
                for (int nj = 0; nj < 4; nj++) {
                    const int bi = nj >> 1, pr = (nj & 1) * 2;
                    mma16816(acc[mi][nj], a[mi], bh[bi][pr], bh[bi][pr + 1]);
                    mma16816(acc[mi][nj], a[mi], bl[bi][pr], bl[bi][pr + 1]);
                }
            }
        }
    }
    asm volatile("cp.async.wait_group 0;\n" ::: "memory");

    // epilogue: write fp32 accumulators to g_cur
    const int r_base = m0 + wm + (lid >> 2);
    const int c_base = n0 + wn + (lid & 3) * 2;
    #pragma unroll
    for (int mi = 0; mi < 4; mi++) {
        #pragma unroll
        for (int nj = 0; nj < 4; nj++) {
            float2 v01 = make_float2(acc[mi][nj][0], acc[mi][nj][1]);
            float2 v23 = make_float2(acc[mi][nj][2], acc[mi][nj][3]);
            *reinterpret_cast<float2*>(
                &g_cur[(size_t)(r_base + mi * 16) * N + c_base + nj * 8]) = v01;
            *reinterpret_cast<float2*>(
                &g_cur[(size_t)(r_base + mi * 16 + 8) * N + c_base + nj * 8]) = v23;
        }
    }
}

// ---------------- LIF scan kernel ----------------
__global__ void scan_kernel(float* __restrict__ out) {
    const int id = blockIdx.x * blockDim.x + threadIdx.x;   // one (b, o) per thread
    const int o = id & (N - 1);
    const int b = id >> 11;
    const float alpha_s = 0.8f;       // 1 - DT/TAU_S
    const float alpha_m = 0.95f;      // 1 - DT/TAU_M
    const float inv_tau = 0.05f;      // DT/TAU_M
    float V = 0.0f, I = 0.0f;
    #pragma unroll
    for (int t = 0; t < T; t++) {
        const size_t idx = ((size_t)(t * B + b)) * N + o;
        float cu = g_cur[idx];
        I = alpha_s * I + cu;
        V = alpha_m * V + inv_tau * I;
        float s = (V >= 1.0f) ? 1.0f : 0.0f;
        out[idx] = s;
        V = (V >= 1.0f) ? 0.0f : V;
    }
}

// ---------------- launch ----------------
extern "C" void kernel_launch(void* const* d_in, const int* in_sizes, int n_in,
                              void* d_out, int out_size) {
    const float* x = (const float*)d_in[0];       // [T, B, IN] fp32, binary
    const float* w = (const float*)d_in[1];       // [OUT, IN]  fp32
    float* out = (float*)d_out;                   // [T, B, OUT] fp32

    cudaFuncSetAttribute(gemm_kernel, cudaFuncAttributeMaxDynamicSharedMemorySize, SMEM_B);

    split_w_kernel<<<(N * K + 255) / 256, 256>>>(w);
    conv_x_kernel<<<(int)(((size_t)M * K / 4 + 255) / 256), 256>>>(x);
    gemm_kernel<<<dim3(N / BN, M / BM), 256, SMEM_B>>>();
    scan_kernel<<<(B * N) / 256, 256>>>(out);
}

// round 6
// speedup vs baseline: 1.0755x; 1.0755x over previous
#include <cuda_runtime.h>
#include <cuda_fp16.h>
#include <cstdint>

// ---------------- Problem dims ----------------
static constexpr int T   = 20;
static constexpr int B   = 1024;
static constexpr int IN  = 2048;
static constexpr int OUT = 2048;
static constexpr int M   = T * B;          // 20480
static constexpr int K   = IN;             // 2048
static constexpr int N   = OUT;            // 2048

// GEMM tiling: 256x128x64 CTA tile, 512 threads (4x4 warps of 64x32), 2 stages
static constexpr int BM = 256;
static constexpr int BN = 128;
static constexpr int BK = 64;
static constexpr int STAGES = 2;
static constexpr int NCHUNK = K / BK;      // 32

static constexpr int PAD     = 72;                  // smem row stride in halfs (144B)
static constexpr int MAT_A_B = 256 * PAD * 2;       // 36864 B  A tile
static constexpr int MAT_W_B = 128 * PAD * 2;       // 18432 B  per W tile
static constexpr int STAGE_B = MAT_A_B + 2 * MAT_W_B;  // 73728 B
static constexpr int SMEM_B  = STAGES * STAGE_B;       // 147456 B

// ---------------- scratch (no cudaMalloc allowed) ----------------
__device__ __half g_xh [(size_t)M * K];    // 84 MB  x in fp16 (exact: x is 0/1)
__device__ __half g_whi[(size_t)N * K];    // 8 MB   weight hi (fp16)
__device__ __half g_wlo[(size_t)N * K];    // 8 MB   weight lo (fp16 residual)
__device__ float  g_cur[(size_t)M * N];    // 168 MB GEMM result (fp32)

// ---------------- helpers ----------------
__device__ __forceinline__ uint32_t smem_u32(const void* p) {
    uint32_t a;
    asm("{ .reg .u64 t; cvta.to.shared.u64 t, %1; cvt.u32.u64 %0, t; }" : "=r"(a) : "l"(p));
    return a;
}
__device__ __forceinline__ void cp16(uint32_t dst, const void* src) {
    asm volatile("cp.async.cg.shared.global [%0], [%1], 16;\n" :: "r"(dst), "l"(src));
}
__device__ __forceinline__ void ldm_x4(uint32_t* r, uint32_t addr) {
    asm volatile("ldmatrix.sync.aligned.m8n8.x4.shared.b16 {%0,%1,%2,%3}, [%4];"
                 : "=r"(r[0]), "=r"(r[1]), "=r"(r[2]), "=r"(r[3]) : "r"(addr));
}
__device__ __forceinline__ void mma16816(float* d, const uint32_t* a, uint32_t b0, uint32_t b1) {
    asm volatile(
        "mma.sync.aligned.m16n8k16.row.col.f32.f16.f16.f32 "
        "{%0,%1,%2,%3}, {%4,%5,%6,%7}, {%8,%9}, {%0,%1,%2,%3};"
        : "+f"(d[0]), "+f"(d[1]), "+f"(d[2]), "+f"(d[3])
        : "r"(a[0]), "r"(a[1]), "r"(a[2]), "r"(a[3]), "r"(b0), "r"(b1));
}

// ---------------- prep kernels ----------------
__global__ void split_w_kernel(const float* __restrict__ w) {
    int i = blockIdx.x * blockDim.x + threadIdx.x;
    if (i < N * K) {
        float v = w[i];
        __half hi = __float2half_rn(v);
        float r = v - __half2float(hi);
        g_whi[i] = hi;
        g_wlo[i] = __float2half_rn(r);
    }
}

__global__ void conv_x_kernel(const float* __restrict__ x) {
    size_t i = (size_t)blockIdx.x * blockDim.x + threadIdx.x;   // one float4 per thread
    if (i < ((size_t)M * K) / 4) {
        float4 v = reinterpret_cast<const float4*>(x)[i];
        __half2 h0 = __floats2half2_rn(v.x, v.y);
        __half2 h1 = __floats2half2_rn(v.z, v.w);
        uint2 packed;
        packed.x = *reinterpret_cast<uint32_t*>(&h0);
        packed.y = *reinterpret_cast<uint32_t*>(&h1);
        reinterpret_cast<uint2*>(g_xh)[i] = packed;
    }
}

// ---------------- GEMM: 256x128x64, 512 thr, 2-stage cp.async, fp16 2-split mma.sync ----
__global__ void __launch_bounds__(512, 1) gemm_kernel() {
    extern __shared__ char smem[];
    const uint32_t sb = smem_u32(smem);
    const int tid = threadIdx.x;
    const int lid = tid & 31;
    const int wid = tid >> 5;

    const int m0 = blockIdx.y * BM;
    const int n0 = blockIdx.x * BN;

    // warp layout: 4 (m) x 4 (n), warp tile 64x32
    const int wm = (wid & 3) * 64;
    const int wn = (wid >> 2) * 32;

    // ldmatrix lane addressing
    const int a_row = wm + (lid & 15);
    const int a_kh  = (lid >> 4) << 3;                         // 0 or 8
    const int b_n   = wn + (lid & 7) + ((lid >> 4) << 3);
    const int b_kh  = ((lid >> 3) & 1) << 3;

    auto issue = [&](int c) {
        if (c < NCHUNK) {
            const int k0 = c * BK;
            const uint32_t base = sb + (c & 1) * STAGE_B;
            // A: 256 rows x 8 x 16B = 2048 cp16 / 512 thr = 4 each
            #pragma unroll
            for (int i = 0; i < 4; i++) {
                int id = tid + i * 512;
                int row = id >> 3, kc = id & 7;
                cp16(base + row * 144 + kc * 16,
                     g_xh + (size_t)(m0 + row) * K + k0 + kc * 8);
            }
            // B hi+lo: 256 rows total (128 hi, 128 lo) = 2048 cp16 / 512 thr = 4 each
            #pragma unroll
            for (int i = 0; i < 4; i++) {
                int id = tid + i * 512;
                int row = id >> 3, kc = id & 7;
                const __half* src = (row < 128)
                    ? g_whi + (size_t)(n0 + row) * K + k0 + kc * 8
                    : g_wlo + (size_t)(n0 + row - 128) * K + k0 + kc * 8;
                uint32_t boff = (row < 128) ? MAT_A_B : (MAT_A_B + MAT_W_B);
                cp16(base + boff + (row & 127) * 144 + kc * 16, src);
            }
        }
        asm volatile("cp.async.commit_group;\n" ::: "memory");
    };

    issue(0);

    float acc[4][4][4];
    #pragma unroll
    for (int i = 0; i < 4; i++)
        #pragma unroll
        for (int j = 0; j < 4; j++)
            #pragma unroll
            for (int r = 0; r < 4; r++) acc[i][j][r] = 0.0f;

    #pragma unroll 1
    for (int c = 0; c < NCHUNK; c++) {
        asm volatile("cp.async.wait_group 0;\n" ::: "memory");
        __syncthreads();
        issue(c + 1);

        const uint32_t sA  = sb + (c & 1) * STAGE_B;
        const uint32_t sBh = sA + MAT_A_B;
        const uint32_t sBl = sA + MAT_A_B + MAT_W_B;

        #pragma unroll
        for (int ks = 0; ks < 4; ks++) {
            uint32_t a[4][4];
            #pragma unroll
            for (int mi = 0; mi < 4; mi++) {
                uint32_t addr = sA + (uint32_t)((a_row + mi * 16) * PAD + ks * 16 + a_kh) * 2;
                ldm_x4(a[mi], addr);
            }
            uint32_t bh[2][4], bl[2][4];
            #pragma unroll
            for (int bi = 0; bi < 2; bi++) {
                uint32_t off = (uint32_t)((b_n + bi * 16) * PAD + ks * 16 + b_kh) * 2;
                ldm_x4(bh[bi], sBh + off);
                ldm_x4(bl[bi], sBl + off);
            }
            #pragma unroll
            for (int mi = 0; mi < 4; mi++) {
                #pragma unroll
                for (int nj = 0; nj < 4; nj++) {
                    const int bi = nj >> 1, pr = (nj & 1) * 2;
                    mma16816(acc[mi][nj], a[mi], bh[bi][pr], bh[bi][pr + 1]);
                    mma16816(acc[mi][nj], a[mi], bl[bi][pr], bl[bi][pr + 1]);
                }
            }
        }
        __syncthreads();
    }

    // epilogue: write fp32 accumulators to g_cur
    const int r_base = m0 + wm + (lid >> 2);
    const int c_base = n0 + wn + (lid & 3) * 2;
    #pragma unroll
    for (int mi = 0; mi < 4; mi++) {
        #pragma unroll
        for (int nj = 0; nj < 4; nj++) {
            float2 v01 = make_float2(acc[mi][nj][0], acc[mi][nj][1]);
            float2 v23 = make_float2(acc[mi][nj][2], acc[mi][nj][3]);
            *reinterpret_cast<float2*>(
                &g_cur[(size_t)(r_base + mi * 16) * N + c_base + nj * 8]) = v01;
            *reinterpret_cast<float2*>(
                &g_cur[(size_t)(r_base + mi * 16 + 8) * N + c_base + nj * 8]) = v23;
        }
    }
}

// ---------------- LIF scan kernel ----------------
__global__ void scan_kernel(float* __restrict__ out) {
    const int id = blockIdx.x * blockDim.x + threadIdx.x;   // one (b, o) per thread
    const int o = id & (N - 1);
    const int b = id >> 11;
    const float alpha_s = 0.8f;       // 1 - DT/TAU_S
    const float alpha_m = 0.95f;      // 1 - DT/TAU_M
    const float inv_tau = 0.05f;      // DT/TAU_M
    float V = 0.0f, I = 0.0f;
    #pragma unroll
    for (int t = 0; t < T; t++) {
        const size_t idx = ((size_t)(t * B + b)) * N + o;
        float cu = g_cur[idx];
        I = alpha_s * I + cu;
        V = alpha_m * V + inv_tau * I;
        float s = (V >= 1.0f) ? 1.0f : 0.0f;
        out[idx] = s;
        V = (V >= 1.0f) ? 0.0f : V;
    }
}

// ---------------- launch ----------------
extern "C" void kernel_launch(void* const* d_in, const int* in_sizes, int n_in,
                              void* d_out, int out_size) {
    const float* x = (const float*)d_in[0];       // [T, B, IN] fp32, binary
    const float* w = (const float*)d_in[1];       // [OUT, IN]  fp32
    float* out = (float*)d_out;                   // [T, B, OUT] fp32

    cudaFuncSetAttribute(gemm_kernel, cudaFuncAttributeMaxDynamicSharedMemorySize, SMEM_B);

    split_w_kernel<<<(N * K + 255) / 256, 256>>>(w);
    conv_x_kernel<<<(int)(((size_t)M * K / 4 + 255) / 256), 256>>>(x);
    gemm_kernel<<<dim3(N / BN, M / BM), 512, SMEM_B>>>();
    scan_kernel<<<(B * N) / 256, 256>>>(out);
}